// round 15
// baseline (speedup 1.0000x reference)
#include <cuda_runtime.h>
#include <cuda_bf16.h>
#include <cuda_fp16.h>
#include <math.h>
#include <stdint.h>
#include <float.h>

#define BATCH 4
#define CCH   1024
#define DCH   128
#define RCH   64
#define NPIX  4096
#define NBLK  32              // N-blocks in the bmm (4096/128)

// ===========================================================================
// Scratch (device globals — allocation-free)
// ===========================================================================
__device__ __nv_bfloat16 g_xThi [(size_t)BATCH * NPIX * CCH];   // x^T  [b][n][c] bf16 hi
__device__ __nv_bfloat16 g_xTlo [(size_t)BATCH * NPIX * CCH];
__device__ __half        g_x1T  [(size_t)BATCH * NPIX * CCH];   // x1^T [b][n][c] fp16 single
__device__ __nv_bfloat16 g_Wqkhi[(size_t)2 * DCH * CCH];        // [256][1024]
__device__ __nv_bfloat16 g_Wqklo[(size_t)2 * DCH * CCH];
__device__ float         g_bqk[2 * DCH];
__device__ __half g_Wvhi16[(size_t)CCH * CCH];                  // Wv fp16 hi
__device__ __half g_Wvlo16[(size_t)CCH * CCH];                  // Wv fp16 lo
__device__ __nv_bfloat16 g_QKThi[(size_t)BATCH * NPIX * 2 * DCH]; // [b][n][256]
__device__ __nv_bfloat16 g_QKTlo[(size_t)BATCH * NPIX * 2 * DCH];
__device__ __half g_Vhi16[(size_t)BATCH * CCH * NPIX];          // [b][c][m] fp16 hi
__device__ __half g_Vlo16[(size_t)BATCH * CCH * NPIX];          // fp16 lo
__device__ __half g_att16[(size_t)BATCH * NPIX * NPIX];         // [b][n][m] fp16
__device__ float g_outpre[(size_t)BATCH * CCH * NPIX];          // [b][c][n] fp32
__device__ float g_ppool[2 * BATCH * NBLK * CCH];               // partial sums | partial maxes
__device__ float g_gate[BATCH * CCH];

// ===========================================================================
// Baseline-PTX helpers (mma.sync / ldmatrix / cp.async only)
// ===========================================================================
__device__ __forceinline__ uint32_t smem_u32(const void* p) {
    uint32_t a;
    asm("{ .reg .u64 t; cvta.to.shared.u64 t, %1; cvt.u32.u64 %0, t; }" : "=r"(a) : "l"(p));
    return a;
}
#define SWZ128(x) ((x) ^ (((x) >> 3) & 0x70))

__device__ __forceinline__ void cpa16(uint32_t s, const void* g) {
    asm volatile("cp.async.cg.shared.global [%0], [%1], 16;" :: "r"(s), "l"(g));
}
#define CP_COMMIT() asm volatile("cp.async.commit_group;" ::: "memory")
#define CP_WAIT0()  asm volatile("cp.async.wait_group 0;"  ::: "memory")

__device__ __forceinline__ void ldm4(uint32_t* r, uint32_t a) {
    asm volatile("ldmatrix.sync.aligned.m8n8.x4.shared.b16 {%0,%1,%2,%3}, [%4];"
        : "=r"(r[0]), "=r"(r[1]), "=r"(r[2]), "=r"(r[3]) : "r"(a));
}
__device__ __forceinline__ void mma_bf(float* d, const uint32_t* a, const uint32_t* b) {
    asm volatile("mma.sync.aligned.m16n8k16.row.col.f32.bf16.bf16.f32 "
        "{%0,%1,%2,%3}, {%4,%5,%6,%7}, {%8,%9}, {%0,%1,%2,%3};"
        : "+f"(d[0]), "+f"(d[1]), "+f"(d[2]), "+f"(d[3])
        : "r"(a[0]), "r"(a[1]), "r"(a[2]), "r"(a[3]), "r"(b[0]), "r"(b[1]));
}
__device__ __forceinline__ void mma_fp(float* d, const uint32_t* a, const uint32_t* b) {
    asm volatile("mma.sync.aligned.m16n8k16.row.col.f32.f16.f16.f32 "
        "{%0,%1,%2,%3}, {%4,%5,%6,%7}, {%8,%9}, {%0,%1,%2,%3};"
        : "+f"(d[0]), "+f"(d[1]), "+f"(d[2]), "+f"(d[3])
        : "r"(a[0]), "r"(a[1]), "r"(a[2]), "r"(a[3]), "r"(b[0]), "r"(b[1]));
}

// ===========================================================================
// Tiled MMA GEMM (math identical to R13)
// ===========================================================================
#define KC 64

template<int MODE> struct StageCfg {
    static constexpr int NOPS  = (MODE == 0) ? 4 : 3;
    static constexpr int BYTES = NOPS * 16384;
};

template<int MODE>
__device__ __forceinline__ void ld_stage(uint32_t sb, int s,
    const uint16_t* __restrict__ Ahi, const uint16_t* __restrict__ Alo, int pitchA,
    const uint16_t* __restrict__ Bhi, const uint16_t* __restrict__ Blo, int pitchB,
    int k0, int tid)
{
    const uint32_t base = sb + s * StageCfg<MODE>::BYTES;
#pragma unroll
    for (int t = 0; t < 4; t++) {
        int i = tid + t * 256;                  // 0..1023
        int row = i >> 3;
        int ch  = (i & 7) * 16;                 // byte offset within 128B row
        uint32_t so = SWZ128((uint32_t)(row * 128 + ch));
        cpa16(base + so,         (const char*)(Ahi + (size_t)row * pitchA + k0) + ch);
        cpa16(base + 16384 + so, (const char*)(Alo + (size_t)row * pitchA + k0) + ch);
        cpa16(base + 32768 + so, (const char*)(Bhi + (size_t)row * pitchB + k0) + ch);
        if (MODE == 0)
            cpa16(base + 49152 + so, (const char*)(Blo + (size_t)row * pitchB + k0) + ch);
    }
}

template<int MODE>
__device__ __forceinline__ void compute_chunk(uint32_t bufbase,
    int wm, int wn, int a_row, int a_kb, int b_noff, int b_kb,
    float acc[2][8][4])
{
    const uint32_t bAH = bufbase;
    const uint32_t bAL = bufbase + 16384;
    const uint32_t bBH = bufbase + 32768;
    const uint32_t bBL = bufbase + 49152;   // MODE 0 only
#pragma unroll
    for (int ks = 0; ks < 4; ks++) {
        const int kb = ks * 32;
        uint32_t ah[2][4], al[2][4];
#pragma unroll
        for (int mt = 0; mt < 2; mt++) {
            uint32_t off = SWZ128((uint32_t)((wm + mt * 16 + a_row) * 128 + kb + a_kb));
            ldm4(ah[mt], bAH + off);
            ldm4(al[mt], bAL + off);
        }
#pragma unroll
        for (int p = 0; p < 4; p++) {
            uint32_t off = SWZ128((uint32_t)((wn + p * 16 + b_noff) * 128 + kb + b_kb));
            uint32_t bhp[4];
            ldm4(bhp, bBH + off);
            if (MODE == 0) {
                uint32_t blp[4];
                ldm4(blp, bBL + off);
#pragma unroll
                for (int mt = 0; mt < 2; mt++) {
                    mma_bf(acc[mt][2 * p],     ah[mt], bhp + 0);
                    mma_bf(acc[mt][2 * p],     ah[mt], blp + 0);
                    mma_bf(acc[mt][2 * p],     al[mt], bhp + 0);
                    mma_bf(acc[mt][2 * p + 1], ah[mt], bhp + 2);
                    mma_bf(acc[mt][2 * p + 1], ah[mt], blp + 2);
                    mma_bf(acc[mt][2 * p + 1], al[mt], bhp + 2);
                }
            } else {
#pragma unroll
                for (int mt = 0; mt < 2; mt++) {
                    mma_fp(acc[mt][2 * p],     ah[mt], bhp + 0);
                    mma_fp(acc[mt][2 * p],     al[mt], bhp + 0);
                    mma_fp(acc[mt][2 * p + 1], ah[mt], bhp + 2);
                    mma_fp(acc[mt][2 * p + 1], al[mt], bhp + 2);
                }
            }
        }
    }
}

template<int KDIM, int EPI, bool SWAP, int MODE, int NSTAGE, int OCC>
__global__ __launch_bounds__(256, OCC)
void mma_gemm(const uint16_t* __restrict__ Ahi, const uint16_t* __restrict__ Alo,
              int pitchA, long long sAb,
              const uint16_t* __restrict__ Bhi, const uint16_t* __restrict__ Blo,
              int pitchB, long long sBb,
              const float* __restrict__ bias,
              void* __restrict__ Cout, void* __restrict__ Caux,
              int pitchC, long long sCb)
{
    extern __shared__ char smem[];
    const uint32_t sb = smem_u32(smem);
    const int tid = threadIdx.x;
    const int bm = (SWAP ? blockIdx.x : blockIdx.y) * 128;
    const int bn = (SWAP ? blockIdx.y : blockIdx.x) * 128;
    const int b  = blockIdx.z;

    Ahi += (size_t)b * sAb + (size_t)bm * pitchA;
    Alo += (size_t)b * sAb + (size_t)bm * pitchA;
    Bhi += (size_t)b * sBb + (size_t)bn * pitchB;
    if (MODE == 0) Blo += (size_t)b * sBb + (size_t)bn * pitchB;

    constexpr int NC = KDIM / KC;
    constexpr int SBYTES = StageCfg<MODE>::BYTES;

    const int w  = tid >> 5, l = tid & 31;
    const int wm = (w & 3) * 32;
    const int wn = (w >> 2) * 64;

    const int a_row  = l & 15;
    const int a_kb   = (l >> 4) * 16;
    const int b_noff = ((l >> 4) & 1) * 8 + (l & 7);
    const int b_kb   = ((l >> 3) & 1) * 16;

    float acc[2][8][4];
#pragma unroll
    for (int i = 0; i < 2; i++)
#pragma unroll
        for (int j = 0; j < 8; j++)
#pragma unroll
            for (int q = 0; q < 4; q++) acc[i][j][q] = 0.f;

    if (NSTAGE == 2) {
        ld_stage<MODE>(sb, 0, Ahi, Alo, pitchA, Bhi, Blo, pitchB, 0, tid);
        CP_COMMIT();
        int buf = 0;
#pragma unroll 1
        for (int c = 0; c < NC; c++) {
            CP_WAIT0();
            __syncthreads();
            if (c + 1 < NC) {
                ld_stage<MODE>(sb, buf ^ 1, Ahi, Alo, pitchA, Bhi, Blo, pitchB, (c + 1) * KC, tid);
                CP_COMMIT();
            }
            compute_chunk<MODE>(sb + buf * SBYTES, wm, wn, a_row, a_kb, b_noff, b_kb, acc);
            buf ^= 1;
        }
    } else {
#pragma unroll 1
        for (int c = 0; c < NC; c++) {
            ld_stage<MODE>(sb, 0, Ahi, Alo, pitchA, Bhi, Blo, pitchB, c * KC, tid);
            CP_COMMIT();
            CP_WAIT0();
            __syncthreads();
            compute_chunk<MODE>(sb, wm, wn, a_row, a_kb, b_noff, b_kb, acc);
            __syncthreads();
        }
    }
    __syncthreads();

    // ---- epilogue: regs -> SMEM stage (fp32, pitch 132) -> coalesced GMEM
    float* stage = (float*)smem;
    {
        const int qr = l >> 2, qc = (l & 3) * 2;
#pragma unroll
        for (int mt = 0; mt < 2; mt++)
#pragma unroll
            for (int nt = 0; nt < 8; nt++) {
                int r0 = wm + mt * 16 + qr;
                int c0 = wn + nt * 8 + qc;
                *(float2*)&stage[(size_t)r0 * 132 + c0] =
                    make_float2(acc[mt][nt][0], acc[mt][nt][1]);
                *(float2*)&stage[(size_t)(r0 + 8) * 132 + c0] =
                    make_float2(acc[mt][nt][2], acc[mt][nt][3]);
            }
    }
    __syncthreads();

    for (int g = tid; g < 2048; g += 256) {
        int row = g >> 4;
        int lc  = (g & 15) * 8;
        const float* st = stage + (size_t)row * 132 + lc;
        int orow = bm + row;
        int ncol = bn + lc;
        float v[8];
#pragma unroll
        for (int j = 0; j < 8; j++) {
            float x = st[j];
            if (EPI == 0) x += bias[ncol + j];
            if (EPI == 1) x += bias[orow];
            if (EPI == 2) x = __fdividef(1.f, 1.f + __expf(-x));
            v[j] = x;
        }
        size_t dsto = (size_t)b * sCb + (size_t)orow * pitchC + ncol;
        if (EPI == 3 || EPI == 4) {
            float* dst = (float*)Cout + dsto;
            *(float4*)dst       = make_float4(v[0], v[1], v[2], v[3]);
            *(float4*)(dst + 4) = make_float4(v[4], v[5], v[6], v[7]);
        } else if (EPI == 2) {
            uint16_t hb[8];
#pragma unroll
            for (int j = 0; j < 8; j++) {
                __half h = __float2half(v[j]);
                hb[j] = *(uint16_t*)&h;
            }
            *(uint4*)((__half*)Cout + dsto) = *(uint4*)hb;
        } else if (EPI == 1) {
            uint16_t hb[8], lb[8];
#pragma unroll
            for (int j = 0; j < 8; j++) {
                __half h = __float2half(v[j]);
                __half lo = __float2half(v[j] - __half2float(h));
                hb[j] = *(uint16_t*)&h;
                lb[j] = *(uint16_t*)&lo;
            }
            *(uint4*)((__half*)Cout + dsto) = *(uint4*)hb;
            *(uint4*)((__half*)Caux + dsto) = *(uint4*)lb;
        } else {
            uint16_t hb[8], lb[8];
#pragma unroll
            for (int j = 0; j < 8; j++) {
                __nv_bfloat16 h = __float2bfloat16(v[j]);
                __nv_bfloat16 lo = __float2bfloat16(v[j] - __bfloat162float(h));
                hb[j] = *(uint16_t*)&h;
                lb[j] = *(uint16_t*)&lo;
            }
            *(uint4*)((__nv_bfloat16*)Cout + dsto) = *(uint4*)hb;
            *(uint4*)((__nv_bfloat16*)Caux + dsto) = *(uint4*)lb;
        }
    }

    // ---- partial pooling (bmm only)
    if (EPI == 4) {
        if (tid < 128) {
            const float* sr = stage + (size_t)tid * 132;
            float s = 0.f, m = -FLT_MAX;
#pragma unroll 16
            for (int j = 0; j < 128; j++) {
                float x = sr[j];
                s += x;
                m = fmaxf(m, x);
            }
            // per-batch launches offset Caux by b*NBLK*CCH on the host; the
            // max region sits at a constant +BATCH*NBLK*CCH internal offset,
            // so both land correctly.
            int idx = ((b * NBLK + (int)blockIdx.y) * CCH) + bm + tid;
            float* psum = (float*)Caux;
            psum[idx]                          = s;
            psum[BATCH * NBLK * CCH + idx]     = m;
        }
    }
}

// ===========================================================================
// Prep kernels
// ===========================================================================
__global__ __launch_bounds__(256)
void transpose_split(const float* __restrict__ src,
                     __nv_bfloat16* __restrict__ dhi, __nv_bfloat16* __restrict__ dlo)
{
    __shared__ float t[32][33];
    const int b = blockIdx.z;
    const int n0 = blockIdx.x * 32, c0 = blockIdx.y * 32;
    const float* s = src + (size_t)b * CCH * NPIX;
    const int tx = threadIdx.x, ty = threadIdx.y;      // (32, 8)
#pragma unroll
    for (int j = 0; j < 32; j += 8)
        t[ty + j][tx] = s[(size_t)(c0 + ty + j) * NPIX + n0 + tx];
    __syncthreads();
    const size_t base = (size_t)b * NPIX * CCH;
#pragma unroll
    for (int j = 0; j < 32; j += 8) {
        float v = t[tx][ty + j];
        __nv_bfloat16 h = __float2bfloat16(v);
        __nv_bfloat16 l = __float2bfloat16(v - __bfloat162float(h));
        size_t off = base + (size_t)(n0 + ty + j) * CCH + c0 + tx;
        dhi[off] = h; dlo[off] = l;
    }
}

__global__ __launch_bounds__(256)
void transpose_half(const float* __restrict__ src, __half* __restrict__ dst)
{
    __shared__ float t[32][33];
    const int b = blockIdx.z;
    const int n0 = blockIdx.x * 32, c0 = blockIdx.y * 32;
    const float* s = src + (size_t)b * CCH * NPIX;
    const int tx = threadIdx.x, ty = threadIdx.y;      // (32, 8)
#pragma unroll
    for (int j = 0; j < 32; j += 8)
        t[ty + j][tx] = s[(size_t)(c0 + ty + j) * NPIX + n0 + tx];
    __syncthreads();
    const size_t base = (size_t)b * NPIX * CCH;
#pragma unroll
    for (int j = 0; j < 32; j += 8)
        dst[base + (size_t)(n0 + ty + j) * CCH + c0 + tx] = __float2half(t[tx][ty + j]);
}

__global__ __launch_bounds__(256)
void prep_wqk(const float* __restrict__ Wq, const float* __restrict__ bq,
              const float* __restrict__ Wk, const float* __restrict__ bk,
              __nv_bfloat16* __restrict__ whi, __nv_bfloat16* __restrict__ wlo,
              float* __restrict__ bqk)
{
    int i = blockIdx.x * 256 + threadIdx.x;
    float v = (i < DCH * CCH) ? Wq[i] : Wk[i - DCH * CCH];
    __nv_bfloat16 h = __float2bfloat16(v);
    whi[i] = h; wlo[i] = __float2bfloat16(v - __bfloat162float(h));
    if (i < 2 * DCH) bqk[i] = (i < DCH) ? bq[i] : bk[i - DCH];
}

__global__ __launch_bounds__(256)
void prep_wv(const float* __restrict__ Wv,
             __half* __restrict__ whi, __half* __restrict__ wlo)
{
    int i = blockIdx.x * 256 + threadIdx.x;
    float v = Wv[i];
    __half h = __float2half(v);
    whi[i] = h; wlo[i] = __float2half(v - __half2float(h));
}

// ===========================================================================
// Gate: fold 32-way partial-pool reduction + CBAM MLP + sigmoid (whole-batch)
// ===========================================================================
__global__ __launch_bounds__(256)
void gate_kernel(const float* __restrict__ ppool,
                 const float* __restrict__ Wca1, const float* __restrict__ Wca2,
                 float* __restrict__ gate)
{
    const int b = blockIdx.x;
    const int tid = threadIdx.x;
    __shared__ float avg_s[CCH], max_s[CCH], h[RCH];

    const float* psum = ppool + (size_t)b * NBLK * CCH;
    const float* pmax = ppool + (size_t)BATCH * NBLK * CCH + (size_t)b * NBLK * CCH;
    for (int c = tid; c < CCH; c += 256) {
        float s = 0.f, m = -FLT_MAX;
#pragma unroll 8
        for (int p = 0; p < NBLK; p++) {
            s += psum[(size_t)p * CCH + c];
            m = fmaxf(m, pmax[(size_t)p * CCH + c]);
        }
        avg_s[c] = s * (1.f / NPIX);
        max_s[c] = m;
    }
    __syncthreads();

    for (int r = tid; r < RCH; r += 256) {
        float s1 = 0.f, s2 = 0.f;
        const float* w = Wca1 + (size_t)r * CCH;
        for (int c = 0; c < CCH; c++) { s1 += w[c] * avg_s[c]; s2 += w[c] * max_s[c]; }
        h[r] = fmaxf(s1, 0.f) + fmaxf(s2, 0.f);
    }
    __syncthreads();

    for (int c = tid; c < CCH; c += 256) {
        float g = 0.f;
        const float* w = Wca2 + (size_t)c * RCH;
#pragma unroll 8
        for (int r = 0; r < RCH; r++) g += w[r] * h[r];
        gate[b * CCH + c] = 1.f / (1.f + expf(-g));
    }
}

__global__ __launch_bounds__(256)
void scale_kernel(const float* __restrict__ outpre, const float* __restrict__ gate,
                  float* __restrict__ out)
{
    size_t i = (size_t)blockIdx.x * 256 + threadIdx.x;
    int row = (int)(i >> 10);
    float g = gate[row];
    float4 v = ((const float4*)outpre)[i];
    v.x *= g; v.y *= g; v.z *= g; v.w *= g;
    ((float4*)out)[i] = v;
}

// ===========================================================================
// Host launcher.  Inputs: x, x1, Wq, bq, Wk, bk, Wv, bv, Wca1, Wca2
// Topology (2 streams total, 6 events — R13-class graph size):
//   main: ts(x) -> prep_wqk -> QK(all) -> att(b)x4 [record evA[b]]
//   s1:   ts(x1) -> prep_wv -> V(all) -> {wait evA[b]; bmm(b)}x4 -> gate -> scale
//   main waits evEnd(s1).
// ===========================================================================
extern "C" void kernel_launch(void* const* d_in, const int* in_sizes, int n_in,
                              void* d_out, int out_size)
{
    const float* x    = (const float*)d_in[0];
    const float* x1   = (const float*)d_in[1];
    const float* Wq   = (const float*)d_in[2];
    const float* bq   = (const float*)d_in[3];
    const float* Wk   = (const float*)d_in[4];
    const float* bk   = (const float*)d_in[5];
    const float* Wv   = (const float*)d_in[6];
    const float* bv   = (const float*)d_in[7];
    const float* Wca1 = (const float*)d_in[8];
    const float* Wca2 = (const float*)d_in[9];
    float* out = (float*)d_out;

    constexpr int SM_QK  = StageCfg<0>::BYTES * 2;   // 131072, 1 CTA
    constexpr int SM_ATT = 128 * 132 * 4;            //  67584, 2 CTAs
    constexpr int SM_M1  = StageCfg<1>::BYTES * 2;   //  98304, 2 CTAs

    static cudaStream_t s1 = nullptr;
    static cudaEvent_t evF = nullptr, evEnd = nullptr;
    static cudaEvent_t evA[BATCH];
    static bool init_done = false;
    if (!init_done) {
        cudaFuncSetAttribute(mma_gemm<1024, 0, false, 0, 2, 1>, cudaFuncAttributeMaxDynamicSharedMemorySize, SM_QK);
        cudaFuncSetAttribute(mma_gemm<128,  2, false, 0, 1, 2>, cudaFuncAttributeMaxDynamicSharedMemorySize, SM_ATT);
        cudaFuncSetAttribute(mma_gemm<1024, 1, false, 1, 2, 2>, cudaFuncAttributeMaxDynamicSharedMemorySize, SM_M1);
        cudaFuncSetAttribute(mma_gemm<4096, 4, true,  1, 2, 2>, cudaFuncAttributeMaxDynamicSharedMemorySize, SM_M1);
        cudaStreamCreateWithFlags(&s1, cudaStreamNonBlocking);
        cudaEventCreateWithFlags(&evF, cudaEventDisableTiming);
        cudaEventCreateWithFlags(&evEnd, cudaEventDisableTiming);
        for (int b = 0; b < BATCH; b++)
            cudaEventCreateWithFlags(&evA[b], cudaEventDisableTiming);
        init_done = true;
    }

    void *pxh,*pxl,*p1t,*pwh,*pwl,*pbqk,*pvh,*pvl,*pqh,*pql,*pVh,*pVl,*pat,*pop,*ppp,*pgate;
    cudaGetSymbolAddress(&pxh, g_xThi);  cudaGetSymbolAddress(&pxl, g_xTlo);
    cudaGetSymbolAddress(&p1t, g_x1T);
    cudaGetSymbolAddress(&pwh, g_Wqkhi); cudaGetSymbolAddress(&pwl, g_Wqklo);
    cudaGetSymbolAddress(&pbqk, g_bqk);
    cudaGetSymbolAddress(&pvh, g_Wvhi16); cudaGetSymbolAddress(&pvl, g_Wvlo16);
    cudaGetSymbolAddress(&pqh, g_QKThi); cudaGetSymbolAddress(&pql, g_QKTlo);
    cudaGetSymbolAddress(&pVh, g_Vhi16); cudaGetSymbolAddress(&pVl, g_Vlo16);
    cudaGetSymbolAddress(&pat, g_att16);
    cudaGetSymbolAddress(&pop, g_outpre);
    cudaGetSymbolAddress(&ppp, g_ppool); cudaGetSymbolAddress(&pgate, g_gate);

    dim3 thr(256);
    dim3 tthr(32, 8);

    const size_t sXT = (size_t)NPIX * CCH;
    const size_t sQK = (size_t)NPIX * 2 * DCH;
    const size_t sVs = (size_t)CCH * NPIX;
    const size_t sAT = (size_t)NPIX * NPIX;

    // ---- fork
    cudaEventRecord(evF, 0);
    cudaStreamWaitEvent(s1, evF, 0);

    // ---- s1: V chain (whole-batch launches)
    transpose_half<<<dim3(NPIX / 32, CCH / 32, BATCH), tthr, 0, s1>>>(x1, (__half*)p1t);
    prep_wv<<<(CCH * CCH) / 256, thr, 0, s1>>>(Wv, (__half*)pvh, (__half*)pvl);
    mma_gemm<1024, 1, false, 1, 2, 2><<<dim3(32, 8, BATCH), thr, SM_M1, s1>>>(
        (const uint16_t*)pvh, (const uint16_t*)pvl, CCH, 0LL,
        (const uint16_t*)p1t, nullptr, CCH, (long long)sXT,
        bv, pVh, pVl, NPIX, (long long)sVs);

    // ---- main: QK (whole) -> att per batch
    transpose_split<<<dim3(NPIX / 32, CCH / 32, BATCH), tthr>>>(x, (__nv_bfloat16*)pxh, (__nv_bfloat16*)pxl);
    prep_wqk<<<(2 * DCH * CCH) / 256, thr>>>(Wq, bq, Wk, bk,
        (__nv_bfloat16*)pwh, (__nv_bfloat16*)pwl, (float*)pbqk);
    mma_gemm<1024, 0, false, 0, 2, 1><<<dim3(2, 32, BATCH), thr, SM_QK>>>(
        (const uint16_t*)pxh, (const uint16_t*)pxl, CCH, (long long)sXT,
        (const uint16_t*)pwh, (const uint16_t*)pwl, CCH, 0LL,
        (const float*)pbqk, pqh, pql, 2 * DCH, (long long)sQK);

    for (int b = 0; b < BATCH; b++) {
        mma_gemm<128, 2, false, 0, 1, 2><<<dim3(32, 32, 1), thr, SM_ATT>>>(
            (const uint16_t*)pqh + b * sQK,       (const uint16_t*)pql + b * sQK,       2 * DCH, 0LL,
            (const uint16_t*)pqh + b * sQK + DCH, (const uint16_t*)pql + b * sQK + DCH, 2 * DCH, 0LL,
            nullptr, (__half*)pat + b * sAT, nullptr, NPIX, 0LL);
        cudaEventRecord(evA[b], 0);
    }

    // ---- s1: bmm per batch (waits att(b); V already sequenced on s1)
    for (int b = 0; b < BATCH; b++) {
        cudaStreamWaitEvent(s1, evA[b], 0);
        mma_gemm<4096, 4, true, 1, 2, 2><<<dim3(8, 32, 1), thr, SM_M1, s1>>>(
            (const uint16_t*)pVh + b * sVs, (const uint16_t*)pVl + b * sVs, NPIX, 0LL,
            (const uint16_t*)pat + b * sAT, nullptr, NPIX, 0LL,
            nullptr, (float*)pop + b * sVs,
            (float*)ppp + (size_t)b * NBLK * CCH,
            NPIX, 0LL);
    }

    // ---- s1: tail (whole-batch)
    gate_kernel<<<BATCH, thr, 0, s1>>>((const float*)ppp, Wca1, Wca2, (float*)pgate);
    scale_kernel<<<(int)(((size_t)BATCH * CCH * NPIX / 4) / 256), thr, 0, s1>>>(
        (const float*)pop, (const float*)pgate, out);
    cudaEventRecord(evEnd, s1);

    // ---- join back into the origin stream
    cudaStreamWaitEvent(0, evEnd, 0);
}

// round 16
// speedup vs baseline: 1.0410x; 1.0410x over previous
#include <cuda_runtime.h>
#include <cuda_bf16.h>
#include <cuda_fp16.h>
#include <math.h>
#include <stdint.h>
#include <float.h>

#define BATCH 4
#define CCH   1024
#define DCH   128
#define RCH   64
#define NPIX  4096
#define NBW   16              // N-blocks in the bmm at 256-wide tiles (4096/256)

// ===========================================================================
// Scratch (device globals — allocation-free)
// ===========================================================================
__device__ __nv_bfloat16 g_xThi [(size_t)BATCH * NPIX * CCH];   // x^T  [b][n][c] bf16 hi
__device__ __nv_bfloat16 g_xTlo [(size_t)BATCH * NPIX * CCH];
__device__ __half        g_x1T  [(size_t)BATCH * NPIX * CCH];   // x1^T [b][n][c] fp16
__device__ __nv_bfloat16 g_Wqkhi[(size_t)2 * DCH * CCH];        // [256][1024]
__device__ __nv_bfloat16 g_Wqklo[(size_t)2 * DCH * CCH];
__device__ float         g_bqk[2 * DCH];
__device__ __half g_Wvhi16[(size_t)CCH * CCH];                  // Wv fp16 hi
__device__ __half g_Wvlo16[(size_t)CCH * CCH];                  // Wv fp16 lo
__device__ __nv_bfloat16 g_QKThi[(size_t)BATCH * NPIX * 2 * DCH]; // [b][n][256]
__device__ __nv_bfloat16 g_QKTlo[(size_t)BATCH * NPIX * 2 * DCH];
__device__ __half g_Vhi16[(size_t)BATCH * CCH * NPIX];          // [b][c][m] fp16 hi
__device__ __half g_Vlo16[(size_t)BATCH * CCH * NPIX];          // fp16 lo
__device__ __half g_att16[(size_t)BATCH * NPIX * NPIX];         // [b][n][m] fp16
__device__ float g_outpre[(size_t)BATCH * CCH * NPIX];          // [b][c][n] fp32
__device__ float g_ppool[2 * BATCH * NBW * CCH];                // partial sums | partial maxes
__device__ float g_gate[BATCH * CCH];

// ===========================================================================
// Baseline-PTX helpers
// ===========================================================================
__device__ __forceinline__ uint32_t smem_u32(const void* p) {
    uint32_t a;
    asm("{ .reg .u64 t; cvta.to.shared.u64 t, %1; cvt.u32.u64 %0, t; }" : "=r"(a) : "l"(p));
    return a;
}
#define SWZ128(x) ((x) ^ (((x) >> 3) & 0x70))

__device__ __forceinline__ void cpa16(uint32_t s, const void* g) {
    asm volatile("cp.async.cg.shared.global [%0], [%1], 16;" :: "r"(s), "l"(g));
}
#define CP_COMMIT() asm volatile("cp.async.commit_group;" ::: "memory")
#define CP_WAIT0()  asm volatile("cp.async.wait_group 0;"  ::: "memory")

__device__ __forceinline__ void ldm4(uint32_t* r, uint32_t a) {
    asm volatile("ldmatrix.sync.aligned.m8n8.x4.shared.b16 {%0,%1,%2,%3}, [%4];"
        : "=r"(r[0]), "=r"(r[1]), "=r"(r[2]), "=r"(r[3]) : "r"(a));
}
__device__ __forceinline__ void mma_bf(float* d, const uint32_t* a, const uint32_t* b) {
    asm volatile("mma.sync.aligned.m16n8k16.row.col.f32.bf16.bf16.f32 "
        "{%0,%1,%2,%3}, {%4,%5,%6,%7}, {%8,%9}, {%0,%1,%2,%3};"
        : "+f"(d[0]), "+f"(d[1]), "+f"(d[2]), "+f"(d[3])
        : "r"(a[0]), "r"(a[1]), "r"(a[2]), "r"(a[3]), "r"(b[0]), "r"(b[1]));
}
__device__ __forceinline__ void mma_fp(float* d, const uint32_t* a, const uint32_t* b) {
    asm volatile("mma.sync.aligned.m16n8k16.row.col.f32.f16.f16.f32 "
        "{%0,%1,%2,%3}, {%4,%5,%6,%7}, {%8,%9}, {%0,%1,%2,%3};"
        : "+f"(d[0]), "+f"(d[1]), "+f"(d[2]), "+f"(d[3])
        : "r"(a[0]), "r"(a[1]), "r"(a[2]), "r"(a[3]), "r"(b[0]), "r"(b[1]));
}

#define KC 64

// ===========================================================================
// Warp-level chunk compute (parametric in wm/wn; shared by 256/512-thr kernels)
// Buffer layout: AH @+0, AL @+16384, BH @+32768, BL @+49152 (MODE0 only)
// ===========================================================================
template<int MODE>
__device__ __forceinline__ void compute_chunk(uint32_t bufbase,
    int wm, int wn, int a_row, int a_kb, int b_noff, int b_kb,
    float acc[2][8][4])
{
    const uint32_t bAH = bufbase;
    const uint32_t bAL = bufbase + 16384;
    const uint32_t bBH = bufbase + 32768;
    const uint32_t bBL = bufbase + 49152;
#pragma unroll
    for (int ks = 0; ks < 4; ks++) {
        const int kb = ks * 32;
        uint32_t ah[2][4], al[2][4];
#pragma unroll
        for (int mt = 0; mt < 2; mt++) {
            uint32_t off = SWZ128((uint32_t)((wm + mt * 16 + a_row) * 128 + kb + a_kb));
            ldm4(ah[mt], bAH + off);
            ldm4(al[mt], bAL + off);
        }
#pragma unroll
        for (int p = 0; p < 4; p++) {
            uint32_t off = SWZ128((uint32_t)((wn + p * 16 + b_noff) * 128 + kb + b_kb));
            uint32_t bhp[4];
            ldm4(bhp, bBH + off);
            if (MODE == 0) {
                uint32_t blp[4];
                ldm4(blp, bBL + off);
#pragma unroll
                for (int mt = 0; mt < 2; mt++) {
                    mma_bf(acc[mt][2 * p],     ah[mt], bhp + 0);
                    mma_bf(acc[mt][2 * p],     ah[mt], blp + 0);
                    mma_bf(acc[mt][2 * p],     al[mt], bhp + 0);
                    mma_bf(acc[mt][2 * p + 1], ah[mt], bhp + 2);
                    mma_bf(acc[mt][2 * p + 1], ah[mt], blp + 2);
                    mma_bf(acc[mt][2 * p + 1], al[mt], bhp + 2);
                }
            } else {
#pragma unroll
                for (int mt = 0; mt < 2; mt++) {
                    mma_fp(acc[mt][2 * p],     ah[mt], bhp + 0);
                    mma_fp(acc[mt][2 * p],     al[mt], bhp + 0);
                    mma_fp(acc[mt][2 * p + 1], ah[mt], bhp + 2);
                    mma_fp(acc[mt][2 * p + 1], al[mt], bhp + 2);
                }
            }
        }
    }
}

// ===========================================================================
// 256-thread kernel (MODE0 only: QK + att) — identical math to R13
// ===========================================================================
template<int MODE> struct StageCfg {
    static constexpr int NOPS  = (MODE == 0) ? 4 : 3;
    static constexpr int BYTES = NOPS * 16384;
};

template<int MODE>
__device__ __forceinline__ void ld_stage(uint32_t sb, int s,
    const uint16_t* __restrict__ Ahi, const uint16_t* __restrict__ Alo, int pitchA,
    const uint16_t* __restrict__ Bhi, const uint16_t* __restrict__ Blo, int pitchB,
    int k0, int tid)
{
    const uint32_t base = sb + s * StageCfg<MODE>::BYTES;
#pragma unroll
    for (int t = 0; t < 4; t++) {
        int i = tid + t * 256;
        int row = i >> 3;
        int ch  = (i & 7) * 16;
        uint32_t so = SWZ128((uint32_t)(row * 128 + ch));
        cpa16(base + so,         (const char*)(Ahi + (size_t)row * pitchA + k0) + ch);
        cpa16(base + 16384 + so, (const char*)(Alo + (size_t)row * pitchA + k0) + ch);
        cpa16(base + 32768 + so, (const char*)(Bhi + (size_t)row * pitchB + k0) + ch);
        if (MODE == 0)
            cpa16(base + 49152 + so, (const char*)(Blo + (size_t)row * pitchB + k0) + ch);
    }
}

// EPI: 0 = bias[col] + bf16 split store, 2 = sigmoid + fp16 store
template<int KDIM, int EPI, int MODE, int NSTAGE, int OCC>
__global__ __launch_bounds__(256, OCC)
void mma_gemm(const uint16_t* __restrict__ Ahi, const uint16_t* __restrict__ Alo,
              int pitchA, long long sAb,
              const uint16_t* __restrict__ Bhi, const uint16_t* __restrict__ Blo,
              int pitchB, long long sBb,
              const float* __restrict__ bias,
              void* __restrict__ Cout, void* __restrict__ Caux,
              int pitchC, long long sCb)
{
    extern __shared__ char smem[];
    const uint32_t sb = smem_u32(smem);
    const int tid = threadIdx.x;
    const int bn = blockIdx.x * 128;
    const int bm = blockIdx.y * 128;
    const int b  = blockIdx.z;

    Ahi += (size_t)b * sAb + (size_t)bm * pitchA;
    Alo += (size_t)b * sAb + (size_t)bm * pitchA;
    Bhi += (size_t)b * sBb + (size_t)bn * pitchB;
    if (MODE == 0) Blo += (size_t)b * sBb + (size_t)bn * pitchB;

    constexpr int NC = KDIM / KC;
    constexpr int SBYTES = StageCfg<MODE>::BYTES;

    const int w  = tid >> 5, l = tid & 31;
    const int wm = (w & 3) * 32;
    const int wn = (w >> 2) * 64;
    const int a_row  = l & 15;
    const int a_kb   = (l >> 4) * 16;
    const int b_noff = ((l >> 4) & 1) * 8 + (l & 7);
    const int b_kb   = ((l >> 3) & 1) * 16;

    float acc[2][8][4];
#pragma unroll
    for (int i = 0; i < 2; i++)
#pragma unroll
        for (int j = 0; j < 8; j++)
#pragma unroll
            for (int q = 0; q < 4; q++) acc[i][j][q] = 0.f;

    if (NSTAGE == 2) {
        ld_stage<MODE>(sb, 0, Ahi, Alo, pitchA, Bhi, Blo, pitchB, 0, tid);
        CP_COMMIT();
        int buf = 0;
#pragma unroll 1
        for (int c = 0; c < NC; c++) {
            CP_WAIT0();
            __syncthreads();
            if (c + 1 < NC) {
                ld_stage<MODE>(sb, buf ^ 1, Ahi, Alo, pitchA, Bhi, Blo, pitchB, (c + 1) * KC, tid);
                CP_COMMIT();
            }
            compute_chunk<MODE>(sb + buf * SBYTES, wm, wn, a_row, a_kb, b_noff, b_kb, acc);
            buf ^= 1;
        }
    } else {
#pragma unroll 1
        for (int c = 0; c < NC; c++) {
            ld_stage<MODE>(sb, 0, Ahi, Alo, pitchA, Bhi, Blo, pitchB, c * KC, tid);
            CP_COMMIT();
            CP_WAIT0();
            __syncthreads();
            compute_chunk<MODE>(sb, wm, wn, a_row, a_kb, b_noff, b_kb, acc);
            __syncthreads();
        }
    }
    __syncthreads();

    // epilogue via SMEM stage (pitch 132)
    float* stage = (float*)smem;
    {
        const int qr = l >> 2, qc = (l & 3) * 2;
#pragma unroll
        for (int mt = 0; mt < 2; mt++)
#pragma unroll
            for (int nt = 0; nt < 8; nt++) {
                int r0 = wm + mt * 16 + qr;
                int c0 = wn + nt * 8 + qc;
                *(float2*)&stage[(size_t)r0 * 132 + c0] =
                    make_float2(acc[mt][nt][0], acc[mt][nt][1]);
                *(float2*)&stage[(size_t)(r0 + 8) * 132 + c0] =
                    make_float2(acc[mt][nt][2], acc[mt][nt][3]);
            }
    }
    __syncthreads();

    for (int g = tid; g < 2048; g += 256) {
        int row = g >> 4;
        int lc  = (g & 15) * 8;
        const float* st = stage + (size_t)row * 132 + lc;
        int orow = bm + row;
        int ncol = bn + lc;
        float v[8];
#pragma unroll
        for (int j = 0; j < 8; j++) {
            float x = st[j];
            if (EPI == 0) x += bias[ncol + j];
            if (EPI == 2) x = __fdividef(1.f, 1.f + __expf(-x));
            v[j] = x;
        }
        size_t dsto = (size_t)b * sCb + (size_t)orow * pitchC + ncol;
        if (EPI == 2) {
            uint16_t hb[8];
#pragma unroll
            for (int j = 0; j < 8; j++) {
                __half h = __float2half(v[j]);
                hb[j] = *(uint16_t*)&h;
            }
            *(uint4*)((__half*)Cout + dsto) = *(uint4*)hb;
        } else {
            uint16_t hb[8], lb[8];
#pragma unroll
            for (int j = 0; j < 8; j++) {
                __nv_bfloat16 h = __float2bfloat16(v[j]);
                __nv_bfloat16 lo = __float2bfloat16(v[j] - __bfloat162float(h));
                hb[j] = *(uint16_t*)&h;
                lb[j] = *(uint16_t*)&lo;
            }
            *(uint4*)((__nv_bfloat16*)Cout + dsto) = *(uint4*)hb;
            *(uint4*)((__nv_bfloat16*)Caux + dsto) = *(uint4*)lb;
        }
    }
}

// ===========================================================================
// 512-thread WIDE kernel (MODE1: fp16 2-term), CTA tile 128(M) x 256(N).
// Stage: AH 16K @0, AL 16K @16384, B 32K (256 rows) @32768 -> 64KB x 2 stages.
// EPI: 1 = bias[row] + fp16 split store   4 = fp32 store + partial pooling
// SWAP: blockIdx.x = M-block (L2-friendly raster for the bmm)
// ===========================================================================
#define WSTAGE 65536
#define SM_WIDE 133120        // max(2*WSTAGE, 128*260*4)

__device__ __forceinline__ void ld_stage_wide(uint32_t sb, int s,
    const uint16_t* __restrict__ Ahi, const uint16_t* __restrict__ Alo, int pitchA,
    const uint16_t* __restrict__ Bhi, int pitchB,
    int k0, int tid)
{
    const uint32_t base = sb + s * WSTAGE;
#pragma unroll
    for (int t = 0; t < 2; t++) {                 // A: 128 rows x 8 f4
        int i = tid + t * 512;
        int row = i >> 3;
        int ch  = (i & 7) * 16;
        uint32_t so = SWZ128((uint32_t)(row * 128 + ch));
        cpa16(base + so,         (const char*)(Ahi + (size_t)row * pitchA + k0) + ch);
        cpa16(base + 16384 + so, (const char*)(Alo + (size_t)row * pitchA + k0) + ch);
    }
#pragma unroll
    for (int t = 0; t < 4; t++) {                 // B: 256 rows x 8 f4
        int i = tid + t * 512;
        int row = i >> 3;
        int ch  = (i & 7) * 16;
        uint32_t so = SWZ128((uint32_t)(row * 128 + ch));
        cpa16(base + 32768 + so, (const char*)(Bhi + (size_t)row * pitchB + k0) + ch);
    }
}

template<int KDIM, int EPI, bool SWAP>
__global__ __launch_bounds__(512, 1)
void mma_gemm_wide(const uint16_t* __restrict__ Ahi, const uint16_t* __restrict__ Alo,
                   int pitchA, long long sAb,
                   const uint16_t* __restrict__ Bhi, int pitchB, long long sBb,
                   const float* __restrict__ bias,
                   void* __restrict__ Cout, void* __restrict__ Caux,
                   int pitchC, long long sCb)
{
    extern __shared__ char smem[];
    const uint32_t sb = smem_u32(smem);
    const int tid = threadIdx.x;
    const int bm = (SWAP ? blockIdx.x : blockIdx.y) * 128;
    const int bn = (SWAP ? blockIdx.y : blockIdx.x) * 256;
    const int b  = blockIdx.z;

    Ahi += (size_t)b * sAb + (size_t)bm * pitchA;
    Alo += (size_t)b * sAb + (size_t)bm * pitchA;
    Bhi += (size_t)b * sBb + (size_t)bn * pitchB;

    constexpr int NC = KDIM / KC;

    const int w  = tid >> 5, l = tid & 31;        // 16 warps: 4(M) x 4(N)
    const int wm = (w & 3) * 32;
    const int wn = (w >> 2) * 64;
    const int a_row  = l & 15;
    const int a_kb   = (l >> 4) * 16;
    const int b_noff = ((l >> 4) & 1) * 8 + (l & 7);
    const int b_kb   = ((l >> 3) & 1) * 16;

    float acc[2][8][4];
#pragma unroll
    for (int i = 0; i < 2; i++)
#pragma unroll
        for (int j = 0; j < 8; j++)
#pragma unroll
            for (int q = 0; q < 4; q++) acc[i][j][q] = 0.f;

    ld_stage_wide(sb, 0, Ahi, Alo, pitchA, Bhi, pitchB, 0, tid);
    CP_COMMIT();
    int buf = 0;
#pragma unroll 1
    for (int c = 0; c < NC; c++) {
        CP_WAIT0();
        __syncthreads();
        if (c + 1 < NC) {
            ld_stage_wide(sb, buf ^ 1, Ahi, Alo, pitchA, Bhi, pitchB, (c + 1) * KC, tid);
            CP_COMMIT();
        }
        compute_chunk<1>(sb + buf * WSTAGE, wm, wn, a_row, a_kb, b_noff, b_kb, acc);
        buf ^= 1;
    }
    __syncthreads();

    // ---- epilogue: stage 128 x 256 fp32, pitch 260
    float* stage = (float*)smem;
    {
        const int qr = l >> 2, qc = (l & 3) * 2;
#pragma unroll
        for (int mt = 0; mt < 2; mt++)
#pragma unroll
            for (int nt = 0; nt < 8; nt++) {
                int r0 = wm + mt * 16 + qr;
                int c0 = wn + nt * 8 + qc;
                *(float2*)&stage[(size_t)r0 * 260 + c0] =
                    make_float2(acc[mt][nt][0], acc[mt][nt][1]);
                *(float2*)&stage[(size_t)(r0 + 8) * 260 + c0] =
                    make_float2(acc[mt][nt][2], acc[mt][nt][3]);
            }
    }
    __syncthreads();

    for (int g = tid; g < 4096; g += 512) {
        int row = g >> 5;
        int lc  = (g & 31) * 8;
        const float* st = stage + (size_t)row * 260 + lc;
        int orow = bm + row;
        int ncol = bn + lc;
        float v[8];
#pragma unroll
        for (int j = 0; j < 8; j++) {
            float x = st[j];
            if (EPI == 1) x += bias[orow];
            v[j] = x;
        }
        size_t dsto = (size_t)b * sCb + (size_t)orow * pitchC + ncol;
        if (EPI == 4) {
            float* dst = (float*)Cout + dsto;
            *(float4*)dst       = make_float4(v[0], v[1], v[2], v[3]);
            *(float4*)(dst + 4) = make_float4(v[4], v[5], v[6], v[7]);
        } else {
            uint16_t hb[8], lb[8];
#pragma unroll
            for (int j = 0; j < 8; j++) {
                __half h = __float2half(v[j]);
                __half lo = __float2half(v[j] - __half2float(h));
                hb[j] = *(uint16_t*)&h;
                lb[j] = *(uint16_t*)&lo;
            }
            *(uint4*)((__half*)Cout + dsto) = *(uint4*)hb;
            *(uint4*)((__half*)Caux + dsto) = *(uint4*)lb;
        }
    }

    // ---- partial pooling (bmm only): 128 rows reduced over 256 cols
    if (EPI == 4) {
        if (tid < 128) {
            const float* sr = stage + (size_t)tid * 260;
            float s = 0.f, m = -FLT_MAX;
#pragma unroll 16
            for (int j = 0; j < 256; j++) {
                float x = sr[j];
                s += x;
                m = fmaxf(m, x);
            }
            int idx = ((b * NBW + (int)blockIdx.y) * CCH) + bm + tid;
            float* psum = (float*)Caux;
            psum[idx]                      = s;
            psum[BATCH * NBW * CCH + idx]  = m;
        }
    }
}

// ===========================================================================
// Prep kernels
// ===========================================================================
__global__ __launch_bounds__(256)
void transpose_split(const float* __restrict__ src,
                     __nv_bfloat16* __restrict__ dhi, __nv_bfloat16* __restrict__ dlo)
{
    __shared__ float t[32][33];
    const int b = blockIdx.z;
    const int n0 = blockIdx.x * 32, c0 = blockIdx.y * 32;
    const float* s = src + (size_t)b * CCH * NPIX;
    const int tx = threadIdx.x, ty = threadIdx.y;
#pragma unroll
    for (int j = 0; j < 32; j += 8)
        t[ty + j][tx] = s[(size_t)(c0 + ty + j) * NPIX + n0 + tx];
    __syncthreads();
    const size_t base = (size_t)b * NPIX * CCH;
#pragma unroll
    for (int j = 0; j < 32; j += 8) {
        float v = t[tx][ty + j];
        __nv_bfloat16 h = __float2bfloat16(v);
        __nv_bfloat16 l = __float2bfloat16(v - __bfloat162float(h));
        size_t off = base + (size_t)(n0 + ty + j) * CCH + c0 + tx;
        dhi[off] = h; dlo[off] = l;
    }
}

__global__ __launch_bounds__(256)
void transpose_half(const float* __restrict__ src, __half* __restrict__ dst)
{
    __shared__ float t[32][33];
    const int b = blockIdx.z;
    const int n0 = blockIdx.x * 32, c0 = blockIdx.y * 32;
    const float* s = src + (size_t)b * CCH * NPIX;
    const int tx = threadIdx.x, ty = threadIdx.y;
#pragma unroll
    for (int j = 0; j < 32; j += 8)
        t[ty + j][tx] = s[(size_t)(c0 + ty + j) * NPIX + n0 + tx];
    __syncthreads();
    const size_t base = (size_t)b * NPIX * CCH;
#pragma unroll
    for (int j = 0; j < 32; j += 8)
        dst[base + (size_t)(n0 + ty + j) * CCH + c0 + tx] = __float2half(t[tx][ty + j]);
}

__global__ __launch_bounds__(256)
void prep_wqk(const float* __restrict__ Wq, const float* __restrict__ bq,
              const float* __restrict__ Wk, const float* __restrict__ bk,
              __nv_bfloat16* __restrict__ whi, __nv_bfloat16* __restrict__ wlo,
              float* __restrict__ bqk)
{
    int i = blockIdx.x * 256 + threadIdx.x;
    float v = (i < DCH * CCH) ? Wq[i] : Wk[i - DCH * CCH];
    __nv_bfloat16 h = __float2bfloat16(v);
    whi[i] = h; wlo[i] = __float2bfloat16(v - __bfloat162float(h));
    if (i < 2 * DCH) bqk[i] = (i < DCH) ? bq[i] : bk[i - DCH];
}

__global__ __launch_bounds__(256)
void prep_wv(const float* __restrict__ Wv,
             __half* __restrict__ whi, __half* __restrict__ wlo)
{
    int i = blockIdx.x * 256 + threadIdx.x;
    float v = Wv[i];
    __half h = __float2half(v);
    whi[i] = h; wlo[i] = __float2half(v - __half2float(h));
}

// ===========================================================================
// Gate: fold NBW-way partial-pool reduction + CBAM MLP + sigmoid
// ===========================================================================
__global__ __launch_bounds__(256)
void gate_kernel(const float* __restrict__ ppool,
                 const float* __restrict__ Wca1, const float* __restrict__ Wca2,
                 float* __restrict__ gate)
{
    const int b = blockIdx.x;
    const int tid = threadIdx.x;
    __shared__ float avg_s[CCH], max_s[CCH], h[RCH];

    const float* psum = ppool + (size_t)b * NBW * CCH;
    const float* pmax = ppool + (size_t)BATCH * NBW * CCH + (size_t)b * NBW * CCH;
    for (int c = tid; c < CCH; c += 256) {
        float s = 0.f, m = -FLT_MAX;
#pragma unroll 8
        for (int p = 0; p < NBW; p++) {
            s += psum[(size_t)p * CCH + c];
            m = fmaxf(m, pmax[(size_t)p * CCH + c]);
        }
        avg_s[c] = s * (1.f / NPIX);
        max_s[c] = m;
    }
    __syncthreads();

    for (int r = tid; r < RCH; r += 256) {
        float s1 = 0.f, s2 = 0.f;
        const float* w = Wca1 + (size_t)r * CCH;
        for (int c = 0; c < CCH; c++) { s1 += w[c] * avg_s[c]; s2 += w[c] * max_s[c]; }
        h[r] = fmaxf(s1, 0.f) + fmaxf(s2, 0.f);
    }
    __syncthreads();

    for (int c = tid; c < CCH; c += 256) {
        float g = 0.f;
        const float* w = Wca2 + (size_t)c * RCH;
#pragma unroll 8
        for (int r = 0; r < RCH; r++) g += w[r] * h[r];
        gate[b * CCH + c] = 1.f / (1.f + expf(-g));
    }
}

__global__ __launch_bounds__(256)
void scale_kernel(const float* __restrict__ outpre, const float* __restrict__ gate,
                  float* __restrict__ out)
{
    size_t i = (size_t)blockIdx.x * 256 + threadIdx.x;
    int row = (int)(i >> 10);
    float g = gate[row];
    float4 v = ((const float4*)outpre)[i];
    v.x *= g; v.y *= g; v.z *= g; v.w *= g;
    ((float4*)out)[i] = v;
}

// ===========================================================================
// Host launcher — R13 topology (2 streams, 2 events), WIDE bmm/V kernels.
// ===========================================================================
extern "C" void kernel_launch(void* const* d_in, const int* in_sizes, int n_in,
                              void* d_out, int out_size)
{
    const float* x    = (const float*)d_in[0];
    const float* x1   = (const float*)d_in[1];
    const float* Wq   = (const float*)d_in[2];
    const float* bq   = (const float*)d_in[3];
    const float* Wk   = (const float*)d_in[4];
    const float* bk   = (const float*)d_in[5];
    const float* Wv   = (const float*)d_in[6];
    const float* bv   = (const float*)d_in[7];
    const float* Wca1 = (const float*)d_in[8];
    const float* Wca2 = (const float*)d_in[9];
    float* out = (float*)d_out;

    constexpr int SM_QK  = StageCfg<0>::BYTES * 2;   // 131072, 1 CTA
    constexpr int SM_ATT = 128 * 132 * 4;            //  67584, 2 CTAs

    static cudaStream_t s1 = nullptr;
    static cudaEvent_t evF = nullptr, evJ = nullptr;
    static bool init_done = false;
    if (!init_done) {
        cudaFuncSetAttribute(mma_gemm<1024, 0, 0, 2, 1>, cudaFuncAttributeMaxDynamicSharedMemorySize, SM_QK);
        cudaFuncSetAttribute(mma_gemm<128,  2, 0, 1, 2>, cudaFuncAttributeMaxDynamicSharedMemorySize, SM_ATT);
        cudaFuncSetAttribute(mma_gemm_wide<1024, 1, false>, cudaFuncAttributeMaxDynamicSharedMemorySize, SM_WIDE);
        cudaFuncSetAttribute(mma_gemm_wide<4096, 4, true >, cudaFuncAttributeMaxDynamicSharedMemorySize, SM_WIDE);
        cudaStreamCreateWithFlags(&s1, cudaStreamNonBlocking);
        cudaEventCreateWithFlags(&evF, cudaEventDisableTiming);
        cudaEventCreateWithFlags(&evJ, cudaEventDisableTiming);
        init_done = true;
    }

    void *pxh,*pxl,*p1t,*pwh,*pwl,*pbqk,*pvh,*pvl,*pqh,*pql,*pVh,*pVl,*pat,*pop,*ppp,*pgate;
    cudaGetSymbolAddress(&pxh, g_xThi);  cudaGetSymbolAddress(&pxl, g_xTlo);
    cudaGetSymbolAddress(&p1t, g_x1T);
    cudaGetSymbolAddress(&pwh, g_Wqkhi); cudaGetSymbolAddress(&pwl, g_Wqklo);
    cudaGetSymbolAddress(&pbqk, g_bqk);
    cudaGetSymbolAddress(&pvh, g_Wvhi16); cudaGetSymbolAddress(&pvl, g_Wvlo16);
    cudaGetSymbolAddress(&pqh, g_QKThi); cudaGetSymbolAddress(&pql, g_QKTlo);
    cudaGetSymbolAddress(&pVh, g_Vhi16); cudaGetSymbolAddress(&pVl, g_Vlo16);
    cudaGetSymbolAddress(&pat, g_att16);
    cudaGetSymbolAddress(&pop, g_outpre);
    cudaGetSymbolAddress(&ppp, g_ppool); cudaGetSymbolAddress(&pgate, g_gate);

    dim3 thr(256);
    dim3 wthr(512);
    dim3 tthr(32, 8);

    const long long sXT = (long long)NPIX * CCH;
    const long long sQK = (long long)NPIX * 2 * DCH;
    const long long sV  = (long long)CCH * NPIX;
    const long long sAT = (long long)NPIX * NPIX;

    // ---- fork: V chain on s1
    cudaEventRecord(evF, 0);
    cudaStreamWaitEvent(s1, evF, 0);

    transpose_half<<<dim3(NPIX / 32, CCH / 32, BATCH), tthr, 0, s1>>>(x1, (__half*)p1t);
    prep_wv<<<(CCH * CCH) / 256, thr, 0, s1>>>(Wv, (__half*)pvh, (__half*)pvl);
    // V[c][m] = Wv @ x1 + bv   (M=1024, N=4096, K=1024)  WIDE 128x256
    mma_gemm_wide<1024, 1, false><<<dim3(NPIX / 256, CCH / 128, BATCH), wthr, SM_WIDE, s1>>>(
        (const uint16_t*)pvh, (const uint16_t*)pvl, CCH, 0LL,
        (const uint16_t*)p1t, CCH, sXT,
        bv, pVh, pVl, NPIX, sV);
    cudaEventRecord(evJ, s1);

    // ---- main: QK -> att (whole-batch)
    transpose_split<<<dim3(NPIX / 32, CCH / 32, BATCH), tthr>>>(x, (__nv_bfloat16*)pxh, (__nv_bfloat16*)pxl);
    prep_wqk<<<(2 * DCH * CCH) / 256, thr>>>(Wq, bq, Wk, bk,
        (__nv_bfloat16*)pwh, (__nv_bfloat16*)pwl, (float*)pbqk);

    mma_gemm<1024, 0, 0, 2, 1><<<dim3(2, 32, BATCH), thr, SM_QK>>>(
        (const uint16_t*)pxh, (const uint16_t*)pxl, CCH, sXT,
        (const uint16_t*)pwh, (const uint16_t*)pwl, CCH, 0LL,
        (const float*)pbqk, pqh, pql, 2 * DCH, sQK);

    mma_gemm<128, 2, 0, 1, 2><<<dim3(32, 32, BATCH), thr, SM_ATT>>>(
        (const uint16_t*)pqh,       (const uint16_t*)pql,       2 * DCH, sQK,
        (const uint16_t*)pqh + DCH, (const uint16_t*)pql + DCH, 2 * DCH, sQK,
        nullptr, pat, nullptr, NPIX, sAT);

    // ---- join: bmm needs both V and att
    cudaStreamWaitEvent(0, evJ, 0);

    // outpre[c][n] = sum_m V[c][m] att[n][m]  (M=1024, N=4096, K=4096)  WIDE
    mma_gemm_wide<4096, 4, true><<<dim3(CCH / 128, NPIX / 256, BATCH), wthr, SM_WIDE>>>(
        (const uint16_t*)pVh, (const uint16_t*)pVl, NPIX, sV,
        (const uint16_t*)pat, NPIX, sAT,
        nullptr, pop, ppp, NPIX, sV);

    // tail
    gate_kernel<<<BATCH, thr>>>((const float*)ppp, Wca1, Wca2, (float*)pgate);
    scale_kernel<<<(int)(((size_t)BATCH * CCH * NPIX / 4) / 256), thr>>>(
        (const float*)pop, (const float*)pgate, out);
}

// round 17
// speedup vs baseline: 1.1529x; 1.1075x over previous
#include <cuda_runtime.h>
#include <cuda_bf16.h>
#include <cuda_fp16.h>
#include <math.h>
#include <stdint.h>
#include <float.h>

#define BATCH 4
#define CCH   1024
#define DCH   128
#define RCH   64
#define NPIX  4096
#define NBLK  32              // N-blocks in the bmm (4096/128)

// ===========================================================================
// Scratch (device globals — allocation-free)
// ===========================================================================
__device__ __nv_bfloat16 g_xThi [(size_t)BATCH * NPIX * CCH];   // x^T  [b][n][c] bf16 hi
__device__ __nv_bfloat16 g_xTlo [(size_t)BATCH * NPIX * CCH];
__device__ __half        g_x1T  [(size_t)BATCH * NPIX * CCH];   // x1^T [b][n][c] fp16 single
__device__ __nv_bfloat16 g_Wqkhi[(size_t)2 * DCH * CCH];        // [256][1024]
__device__ __nv_bfloat16 g_Wqklo[(size_t)2 * DCH * CCH];
__device__ float         g_bqk[2 * DCH];
__device__ __half g_Wvhi16[(size_t)CCH * CCH];                  // Wv fp16 hi
__device__ __half g_Wvlo16[(size_t)CCH * CCH];                  // Wv fp16 lo
__device__ __nv_bfloat16 g_QKThi[(size_t)BATCH * NPIX * 2 * DCH]; // [b][n][256]
__device__ __nv_bfloat16 g_QKTlo[(size_t)BATCH * NPIX * 2 * DCH];
__device__ __half g_Vhi16[(size_t)BATCH * CCH * NPIX];          // [b][c][m] fp16 hi
__device__ __half g_Vlo16[(size_t)BATCH * CCH * NPIX];          // fp16 lo
__device__ __half g_att16[(size_t)BATCH * NPIX * NPIX];         // [b][n][m] fp16
__device__ __half g_outpre[(size_t)BATCH * CCH * NPIX];         // [b][c][n] fp16 (NEW)
__device__ float g_ppool[2 * BATCH * NBLK * CCH];               // partial sums | partial maxes
__device__ float g_gate[BATCH * CCH];

// ===========================================================================
// Baseline-PTX helpers (mma.sync / ldmatrix / cp.async only)
// ===========================================================================
__device__ __forceinline__ uint32_t smem_u32(const void* p) {
    uint32_t a;
    asm("{ .reg .u64 t; cvta.to.shared.u64 t, %1; cvt.u32.u64 %0, t; }" : "=r"(a) : "l"(p));
    return a;
}
#define SWZ128(x) ((x) ^ (((x) >> 3) & 0x70))

__device__ __forceinline__ void cpa16(uint32_t s, const void* g) {
    asm volatile("cp.async.cg.shared.global [%0], [%1], 16;" :: "r"(s), "l"(g));
}
#define CP_COMMIT() asm volatile("cp.async.commit_group;" ::: "memory")
#define CP_WAIT0()  asm volatile("cp.async.wait_group 0;"  ::: "memory")

__device__ __forceinline__ void ldm4(uint32_t* r, uint32_t a) {
    asm volatile("ldmatrix.sync.aligned.m8n8.x4.shared.b16 {%0,%1,%2,%3}, [%4];"
        : "=r"(r[0]), "=r"(r[1]), "=r"(r[2]), "=r"(r[3]) : "r"(a));
}
__device__ __forceinline__ void mma_bf(float* d, const uint32_t* a, const uint32_t* b) {
    asm volatile("mma.sync.aligned.m16n8k16.row.col.f32.bf16.bf16.f32 "
        "{%0,%1,%2,%3}, {%4,%5,%6,%7}, {%8,%9}, {%0,%1,%2,%3};"
        : "+f"(d[0]), "+f"(d[1]), "+f"(d[2]), "+f"(d[3])
        : "r"(a[0]), "r"(a[1]), "r"(a[2]), "r"(a[3]), "r"(b[0]), "r"(b[1]));
}
__device__ __forceinline__ void mma_fp(float* d, const uint32_t* a, const uint32_t* b) {
    asm volatile("mma.sync.aligned.m16n8k16.row.col.f32.f16.f16.f32 "
        "{%0,%1,%2,%3}, {%4,%5,%6,%7}, {%8,%9}, {%0,%1,%2,%3};"
        : "+f"(d[0]), "+f"(d[1]), "+f"(d[2]), "+f"(d[3])
        : "r"(a[0]), "r"(a[1]), "r"(a[2]), "r"(a[3]), "r"(b[0]), "r"(b[1]));
}

// ===========================================================================
// Tiled MMA GEMM (identical structure/math to R13)
// ===========================================================================
#define KC 64

template<int MODE> struct StageCfg {
    static constexpr int NOPS  = (MODE == 0) ? 4 : 3;
    static constexpr int BYTES = NOPS * 16384;
};

template<int MODE>
__device__ __forceinline__ void ld_stage(uint32_t sb, int s,
    const uint16_t* __restrict__ Ahi, const uint16_t* __restrict__ Alo, int pitchA,
    const uint16_t* __restrict__ Bhi, const uint16_t* __restrict__ Blo, int pitchB,
    int k0, int tid)
{
    const uint32_t base = sb + s * StageCfg<MODE>::BYTES;
#pragma unroll
    for (int t = 0; t < 4; t++) {
        int i = tid + t * 256;                  // 0..1023
        int row = i >> 3;
        int ch  = (i & 7) * 16;                 // byte offset within 128B row
        uint32_t so = SWZ128((uint32_t)(row * 128 + ch));
        cpa16(base + so,         (const char*)(Ahi + (size_t)row * pitchA + k0) + ch);
        cpa16(base + 16384 + so, (const char*)(Alo + (size_t)row * pitchA + k0) + ch);
        cpa16(base + 32768 + so, (const char*)(Bhi + (size_t)row * pitchB + k0) + ch);
        if (MODE == 0)
            cpa16(base + 49152 + so, (const char*)(Blo + (size_t)row * pitchB + k0) + ch);
    }
}

template<int MODE>
__device__ __forceinline__ void compute_chunk(uint32_t bufbase,
    int wm, int wn, int a_row, int a_kb, int b_noff, int b_kb,
    float acc[2][8][4])
{
    const uint32_t bAH = bufbase;
    const uint32_t bAL = bufbase + 16384;
    const uint32_t bBH = bufbase + 32768;
    const uint32_t bBL = bufbase + 49152;   // MODE 0 only
#pragma unroll
    for (int ks = 0; ks < 4; ks++) {
        const int kb = ks * 32;
        uint32_t ah[2][4], al[2][4];
#pragma unroll
        for (int mt = 0; mt < 2; mt++) {
            uint32_t off = SWZ128((uint32_t)((wm + mt * 16 + a_row) * 128 + kb + a_kb));
            ldm4(ah[mt], bAH + off);
            ldm4(al[mt], bAL + off);
        }
#pragma unroll
        for (int p = 0; p < 4; p++) {
            uint32_t off = SWZ128((uint32_t)((wn + p * 16 + b_noff) * 128 + kb + b_kb));
            uint32_t bhp[4];
            ldm4(bhp, bBH + off);
            if (MODE == 0) {
                uint32_t blp[4];
                ldm4(blp, bBL + off);
#pragma unroll
                for (int mt = 0; mt < 2; mt++) {
                    mma_bf(acc[mt][2 * p],     ah[mt], bhp + 0);
                    mma_bf(acc[mt][2 * p],     ah[mt], blp + 0);
                    mma_bf(acc[mt][2 * p],     al[mt], bhp + 0);
                    mma_bf(acc[mt][2 * p + 1], ah[mt], bhp + 2);
                    mma_bf(acc[mt][2 * p + 1], ah[mt], blp + 2);
                    mma_bf(acc[mt][2 * p + 1], al[mt], bhp + 2);
                }
            } else {
#pragma unroll
                for (int mt = 0; mt < 2; mt++) {
                    mma_fp(acc[mt][2 * p],     ah[mt], bhp + 0);
                    mma_fp(acc[mt][2 * p],     al[mt], bhp + 0);
                    mma_fp(acc[mt][2 * p + 1], ah[mt], bhp + 2);
                    mma_fp(acc[mt][2 * p + 1], al[mt], bhp + 2);
                }
            }
        }
    }
}

// EPI: 0 = bias[col] + bf16 split store   1 = bias[row] + fp16 split store
//      2 = sigmoid + fp16 single store    4 = fp16 store + partial pooling
template<int KDIM, int EPI, bool SWAP, int MODE, int NSTAGE, int OCC>
__global__ __launch_bounds__(256, OCC)
void mma_gemm(const uint16_t* __restrict__ Ahi, const uint16_t* __restrict__ Alo,
              int pitchA, long long sAb,
              const uint16_t* __restrict__ Bhi, const uint16_t* __restrict__ Blo,
              int pitchB, long long sBb,
              const float* __restrict__ bias,
              void* __restrict__ Cout, void* __restrict__ Caux,
              int pitchC, long long sCb)
{
    extern __shared__ char smem[];
    const uint32_t sb = smem_u32(smem);
    const int tid = threadIdx.x;
    const int bm = (SWAP ? blockIdx.x : blockIdx.y) * 128;
    const int bn = (SWAP ? blockIdx.y : blockIdx.x) * 128;
    const int b  = blockIdx.z;

    Ahi += (size_t)b * sAb + (size_t)bm * pitchA;
    Alo += (size_t)b * sAb + (size_t)bm * pitchA;
    Bhi += (size_t)b * sBb + (size_t)bn * pitchB;
    if (MODE == 0) Blo += (size_t)b * sBb + (size_t)bn * pitchB;

    constexpr int NC = KDIM / KC;
    constexpr int SBYTES = StageCfg<MODE>::BYTES;

    const int w  = tid >> 5, l = tid & 31;
    const int wm = (w & 3) * 32;
    const int wn = (w >> 2) * 64;
    const int a_row  = l & 15;
    const int a_kb   = (l >> 4) * 16;
    const int b_noff = ((l >> 4) & 1) * 8 + (l & 7);
    const int b_kb   = ((l >> 3) & 1) * 16;

    float acc[2][8][4];
#pragma unroll
    for (int i = 0; i < 2; i++)
#pragma unroll
        for (int j = 0; j < 8; j++)
#pragma unroll
            for (int q = 0; q < 4; q++) acc[i][j][q] = 0.f;

    if (NSTAGE == 2) {
        ld_stage<MODE>(sb, 0, Ahi, Alo, pitchA, Bhi, Blo, pitchB, 0, tid);
        CP_COMMIT();
        int buf = 0;
#pragma unroll 1
        for (int c = 0; c < NC; c++) {
            CP_WAIT0();
            __syncthreads();
            if (c + 1 < NC) {
                ld_stage<MODE>(sb, buf ^ 1, Ahi, Alo, pitchA, Bhi, Blo, pitchB, (c + 1) * KC, tid);
                CP_COMMIT();
            }
            compute_chunk<MODE>(sb + buf * SBYTES, wm, wn, a_row, a_kb, b_noff, b_kb, acc);
            buf ^= 1;
        }
    } else {
#pragma unroll 1
        for (int c = 0; c < NC; c++) {
            ld_stage<MODE>(sb, 0, Ahi, Alo, pitchA, Bhi, Blo, pitchB, c * KC, tid);
            CP_COMMIT();
            CP_WAIT0();
            __syncthreads();
            compute_chunk<MODE>(sb, wm, wn, a_row, a_kb, b_noff, b_kb, acc);
            __syncthreads();
        }
    }
    __syncthreads();

    // ---- epilogue: regs -> SMEM stage (fp32, pitch 132) -> coalesced GMEM
    float* stage = (float*)smem;
    {
        const int qr = l >> 2, qc = (l & 3) * 2;
#pragma unroll
        for (int mt = 0; mt < 2; mt++)
#pragma unroll
            for (int nt = 0; nt < 8; nt++) {
                int r0 = wm + mt * 16 + qr;
                int c0 = wn + nt * 8 + qc;
                *(float2*)&stage[(size_t)r0 * 132 + c0] =
                    make_float2(acc[mt][nt][0], acc[mt][nt][1]);
                *(float2*)&stage[(size_t)(r0 + 8) * 132 + c0] =
                    make_float2(acc[mt][nt][2], acc[mt][nt][3]);
            }
    }
    __syncthreads();

    for (int g = tid; g < 2048; g += 256) {
        int row = g >> 4;
        int lc  = (g & 15) * 8;
        const float* st = stage + (size_t)row * 132 + lc;
        int orow = bm + row;
        int ncol = bn + lc;
        float v[8];
#pragma unroll
        for (int j = 0; j < 8; j++) {
            float x = st[j];
            if (EPI == 0) x += bias[ncol + j];
            if (EPI == 1) x += bias[orow];
            if (EPI == 2) x = __fdividef(1.f, 1.f + __expf(-x));
            v[j] = x;
        }
        size_t dsto = (size_t)b * sCb + (size_t)orow * pitchC + ncol;
        if (EPI == 4 || EPI == 2) {
            uint16_t hb[8];
#pragma unroll
            for (int j = 0; j < 8; j++) {
                __half h = __float2half(v[j]);
                hb[j] = *(uint16_t*)&h;
            }
            *(uint4*)((__half*)Cout + dsto) = *(uint4*)hb;
        } else if (EPI == 1) {
            uint16_t hb[8], lb[8];
#pragma unroll
            for (int j = 0; j < 8; j++) {
                __half h = __float2half(v[j]);
                __half lo = __float2half(v[j] - __half2float(h));
                hb[j] = *(uint16_t*)&h;
                lb[j] = *(uint16_t*)&lo;
            }
            *(uint4*)((__half*)Cout + dsto) = *(uint4*)hb;
            *(uint4*)((__half*)Caux + dsto) = *(uint4*)lb;
        } else {
            uint16_t hb[8], lb[8];
#pragma unroll
            for (int j = 0; j < 8; j++) {
                __nv_bfloat16 h = __float2bfloat16(v[j]);
                __nv_bfloat16 lo = __float2bfloat16(v[j] - __bfloat162float(h));
                hb[j] = *(uint16_t*)&h;
                lb[j] = *(uint16_t*)&lo;
            }
            *(uint4*)((__nv_bfloat16*)Cout + dsto) = *(uint4*)hb;
            *(uint4*)((__nv_bfloat16*)Caux + dsto) = *(uint4*)lb;
        }
    }

    // ---- partial pooling (bmm only): fp32 stage values (pre-fp16-rounding)
    if (EPI == 4) {
        if (tid < 128) {
            const float* sr = stage + (size_t)tid * 132;
            float s = 0.f, m = -FLT_MAX;
#pragma unroll 16
            for (int j = 0; j < 128; j++) {
                float x = sr[j];
                s += x;
                m = fmaxf(m, x);
            }
            int idx = ((b * NBLK + (int)blockIdx.y) * CCH) + bm + tid;   // SWAP: y = n-block
            float* psum = (float*)Caux;
            psum[idx]                          = s;
            psum[BATCH * NBLK * CCH + idx]     = m;
        }
    }
}

// ===========================================================================
// Prep kernels (vectorized transposes; identical hi/lo arithmetic)
// ===========================================================================
__global__ __launch_bounds__(256)
void transpose_split(const float* __restrict__ src,
                     __nv_bfloat16* __restrict__ dhi, __nv_bfloat16* __restrict__ dlo)
{
    __shared__ float t[64][33];
    const int b = blockIdx.z;
    const int n0 = blockIdx.x * 32, c0 = blockIdx.y * 64;
    const float* s = src + (size_t)b * CCH * NPIX;
    const int tx = threadIdx.x, ty = threadIdx.y;      // (32, 8)
#pragma unroll
    for (int j = 0; j < 64; j += 8)
        t[ty + j][tx] = s[(size_t)(c0 + ty + j) * NPIX + n0 + tx];
    __syncthreads();
    const size_t base = (size_t)b * NPIX * CCH;
    const int tid = ty * 32 + tx;
#pragma unroll
    for (int k = 0; k < 4; k++) {
        int wv = tid + k * 256;            // 0..1023: 32 n-rows x 32 c-pairs
        int n  = wv >> 5;
        int cp = wv & 31;
        float v0 = t[cp * 2][n];
        float v1 = t[cp * 2 + 1][n];
        __nv_bfloat16 h0 = __float2bfloat16(v0);
        __nv_bfloat16 h1 = __float2bfloat16(v1);
        __nv_bfloat16 l0 = __float2bfloat16(v0 - __bfloat162float(h0));
        __nv_bfloat16 l1 = __float2bfloat16(v1 - __bfloat162float(h1));
        uint32_t hp = (uint32_t)(*(uint16_t*)&h0) | ((uint32_t)(*(uint16_t*)&h1) << 16);
        uint32_t lp = (uint32_t)(*(uint16_t*)&l0) | ((uint32_t)(*(uint16_t*)&l1) << 16);
        size_t off = base + (size_t)(n0 + n) * CCH + c0 + cp * 2;
        *(uint32_t*)(dhi + off) = hp;
        *(uint32_t*)(dlo + off) = lp;
    }
}

__global__ __launch_bounds__(256)
void transpose_half(const float* __restrict__ src, __half* __restrict__ dst)
{
    __shared__ float t[64][33];
    const int b = blockIdx.z;
    const int n0 = blockIdx.x * 32, c0 = blockIdx.y * 64;
    const float* s = src + (size_t)b * CCH * NPIX;
    const int tx = threadIdx.x, ty = threadIdx.y;      // (32, 8)
#pragma unroll
    for (int j = 0; j < 64; j += 8)
        t[ty + j][tx] = s[(size_t)(c0 + ty + j) * NPIX + n0 + tx];
    __syncthreads();
    const size_t base = (size_t)b * NPIX * CCH;
    const int tid = ty * 32 + tx;
#pragma unroll
    for (int k = 0; k < 4; k++) {
        int wv = tid + k * 256;
        int n  = wv >> 5;
        int cp = wv & 31;
        __half h0 = __float2half(t[cp * 2][n]);
        __half h1 = __float2half(t[cp * 2 + 1][n]);
        uint32_t hp = (uint32_t)(*(uint16_t*)&h0) | ((uint32_t)(*(uint16_t*)&h1) << 16);
        *(uint32_t*)(dst + base + (size_t)(n0 + n) * CCH + c0 + cp * 2) = hp;
    }
}

__global__ __launch_bounds__(256)
void prep_wqk(const float* __restrict__ Wq, const float* __restrict__ bq,
              const float* __restrict__ Wk, const float* __restrict__ bk,
              __nv_bfloat16* __restrict__ whi, __nv_bfloat16* __restrict__ wlo,
              float* __restrict__ bqk)
{
    int i = blockIdx.x * 256 + threadIdx.x;
    float v = (i < DCH * CCH) ? Wq[i] : Wk[i - DCH * CCH];
    __nv_bfloat16 h = __float2bfloat16(v);
    whi[i] = h; wlo[i] = __float2bfloat16(v - __bfloat162float(h));
    if (i < 2 * DCH) bqk[i] = (i < DCH) ? bq[i] : bk[i - DCH];
}

__global__ __launch_bounds__(256)
void prep_wv(const float* __restrict__ Wv,
             __half* __restrict__ whi, __half* __restrict__ wlo)
{
    int i = blockIdx.x * 256 + threadIdx.x;
    float v = Wv[i];
    __half h = __float2half(v);
    whi[i] = h; wlo[i] = __float2half(v - __half2float(h));
}

// ===========================================================================
// Gate: fold 32-way partial-pool reduction + CBAM MLP + sigmoid
// ===========================================================================
__global__ __launch_bounds__(256)
void gate_kernel(const float* __restrict__ ppool,
                 const float* __restrict__ Wca1, const float* __restrict__ Wca2,
                 float* __restrict__ gate)
{
    const int b = blockIdx.x;
    const int tid = threadIdx.x;
    __shared__ float avg_s[CCH], max_s[CCH], h[RCH];

    const float* psum = ppool + (size_t)b * NBLK * CCH;
    const float* pmax = ppool + (size_t)BATCH * NBLK * CCH + (size_t)b * NBLK * CCH;
    for (int c = tid; c < CCH; c += 256) {
        float s = 0.f, m = -FLT_MAX;
#pragma unroll 8
        for (int p = 0; p < NBLK; p++) {
            s += psum[(size_t)p * CCH + c];
            m = fmaxf(m, pmax[(size_t)p * CCH + c]);
        }
        avg_s[c] = s * (1.f / NPIX);
        max_s[c] = m;
    }
    __syncthreads();

    for (int r = tid; r < RCH; r += 256) {
        float s1 = 0.f, s2 = 0.f;
        const float* w = Wca1 + (size_t)r * CCH;
        for (int c = 0; c < CCH; c++) { s1 += w[c] * avg_s[c]; s2 += w[c] * max_s[c]; }
        h[r] = fmaxf(s1, 0.f) + fmaxf(s2, 0.f);
    }
    __syncthreads();

    for (int c = tid; c < CCH; c += 256) {
        float g = 0.f;
        const float* w = Wca2 + (size_t)c * RCH;
#pragma unroll 8
        for (int r = 0; r < RCH; r++) g += w[r] * h[r];
        gate[b * CCH + c] = 1.f / (1.f + expf(-g));
    }
}

// scale: read fp16 outpre (uint4 = 8 halves), write fp32 out
__global__ __launch_bounds__(256)
void scale_kernel(const __half* __restrict__ outpre, const float* __restrict__ gate,
                  float* __restrict__ out)
{
    size_t i = (size_t)blockIdx.x * 256 + threadIdx.x;   // uint4 index (8 halves)
    int row = (int)(i >> 9);                             // NPIX/8 = 512 per row
    float g = gate[row];
    uint4 v = ((const uint4*)outpre)[i];
    const __half2* hp = (const __half2*)&v;
    float4 o0, o1;
    float2 a;
    a = __half22float2(hp[0]); o0.x = a.x * g; o0.y = a.y * g;
    a = __half22float2(hp[1]); o0.z = a.x * g; o0.w = a.y * g;
    a = __half22float2(hp[2]); o1.x = a.x * g; o1.y = a.y * g;
    a = __half22float2(hp[3]); o1.z = a.x * g; o1.w = a.y * g;
    ((float4*)out)[i * 2]     = o0;
    ((float4*)out)[i * 2 + 1] = o1;
}

// ===========================================================================
// Host launcher — exact R13 topology (2 streams, 2 events).
// ===========================================================================
extern "C" void kernel_launch(void* const* d_in, const int* in_sizes, int n_in,
                              void* d_out, int out_size)
{
    const float* x    = (const float*)d_in[0];
    const float* x1   = (const float*)d_in[1];
    const float* Wq   = (const float*)d_in[2];
    const float* bq   = (const float*)d_in[3];
    const float* Wk   = (const float*)d_in[4];
    const float* bk   = (const float*)d_in[5];
    const float* Wv   = (const float*)d_in[6];
    const float* bv   = (const float*)d_in[7];
    const float* Wca1 = (const float*)d_in[8];
    const float* Wca2 = (const float*)d_in[9];
    float* out = (float*)d_out;

    constexpr int SM_QK  = StageCfg<0>::BYTES * 2;   // 131072, 1 CTA
    constexpr int SM_ATT = 128 * 132 * 4;            //  67584, 2 CTAs
    constexpr int SM_M1  = StageCfg<1>::BYTES * 2;   //  98304, 2 CTAs

    static cudaStream_t s1 = nullptr;
    static cudaEvent_t evF = nullptr, evJ = nullptr;
    static bool init_done = false;
    if (!init_done) {
        cudaFuncSetAttribute(mma_gemm<1024, 0, false, 0, 2, 1>, cudaFuncAttributeMaxDynamicSharedMemorySize, SM_QK);
        cudaFuncSetAttribute(mma_gemm<128,  2, false, 0, 1, 2>, cudaFuncAttributeMaxDynamicSharedMemorySize, SM_ATT);
        cudaFuncSetAttribute(mma_gemm<1024, 1, false, 1, 2, 2>, cudaFuncAttributeMaxDynamicSharedMemorySize, SM_M1);
        cudaFuncSetAttribute(mma_gemm<4096, 4, true,  1, 2, 2>, cudaFuncAttributeMaxDynamicSharedMemorySize, SM_M1);
        cudaStreamCreateWithFlags(&s1, cudaStreamNonBlocking);
        cudaEventCreateWithFlags(&evF, cudaEventDisableTiming);
        cudaEventCreateWithFlags(&evJ, cudaEventDisableTiming);
        init_done = true;
    }

    void *pxh,*pxl,*p1t,*pwh,*pwl,*pbqk,*pvh,*pvl,*pqh,*pql,*pVh,*pVl,*pat,*pop,*ppp,*pgate;
    cudaGetSymbolAddress(&pxh, g_xThi);  cudaGetSymbolAddress(&pxl, g_xTlo);
    cudaGetSymbolAddress(&p1t, g_x1T);
    cudaGetSymbolAddress(&pwh, g_Wqkhi); cudaGetSymbolAddress(&pwl, g_Wqklo);
    cudaGetSymbolAddress(&pbqk, g_bqk);
    cudaGetSymbolAddress(&pvh, g_Wvhi16); cudaGetSymbolAddress(&pvl, g_Wvlo16);
    cudaGetSymbolAddress(&pqh, g_QKThi); cudaGetSymbolAddress(&pql, g_QKTlo);
    cudaGetSymbolAddress(&pVh, g_Vhi16); cudaGetSymbolAddress(&pVl, g_Vlo16);
    cudaGetSymbolAddress(&pat, g_att16);
    cudaGetSymbolAddress(&pop, g_outpre);
    cudaGetSymbolAddress(&ppp, g_ppool); cudaGetSymbolAddress(&pgate, g_gate);

    dim3 thr(256);
    dim3 tthr(32, 8);

    const long long sXT = (long long)NPIX * CCH;
    const long long sQK = (long long)NPIX * 2 * DCH;
    const long long sV  = (long long)CCH * NPIX;
    const long long sAT = (long long)NPIX * NPIX;

    // ---- fork: V chain on s1
    cudaEventRecord(evF, 0);
    cudaStreamWaitEvent(s1, evF, 0);

    transpose_half<<<dim3(NPIX / 32, CCH / 64, BATCH), tthr, 0, s1>>>(x1, (__half*)p1t);
    prep_wv<<<(CCH * CCH) / 256, thr, 0, s1>>>(Wv, (__half*)pvh, (__half*)pvl);
    // V[c][m] = Wv @ x1 + bv   (M=1024, N=4096, K=1024)  fp16 2-term, 2 CTAs/SM
    mma_gemm<1024, 1, false, 1, 2, 2><<<dim3(32, 8, BATCH), thr, SM_M1, s1>>>(
        (const uint16_t*)pvh, (const uint16_t*)pvl, CCH, 0LL,
        (const uint16_t*)p1t, nullptr, CCH, sXT,
        bv, pVh, pVl, NPIX, sV);
    cudaEventRecord(evJ, s1);

    // ---- main: QK -> att (whole-batch)
    transpose_split<<<dim3(NPIX / 32, CCH / 64, BATCH), tthr>>>(x, (__nv_bfloat16*)pxh, (__nv_bfloat16*)pxl);
    prep_wqk<<<(2 * DCH * CCH) / 256, thr>>>(Wq, bq, Wk, bk,
        (__nv_bfloat16*)pwh, (__nv_bfloat16*)pwl, (float*)pbqk);

    mma_gemm<1024, 0, false, 0, 2, 1><<<dim3(2, 32, BATCH), thr, SM_QK>>>(
        (const uint16_t*)pxh, (const uint16_t*)pxl, CCH, sXT,
        (const uint16_t*)pwh, (const uint16_t*)pwl, CCH, 0LL,
        (const float*)pbqk, pqh, pql, 2 * DCH, sQK);

    mma_gemm<128, 2, false, 0, 1, 2><<<dim3(32, 32, BATCH), thr, SM_ATT>>>(
        (const uint16_t*)pqh,       (const uint16_t*)pql,       2 * DCH, sQK,
        (const uint16_t*)pqh + DCH, (const uint16_t*)pql + DCH, 2 * DCH, sQK,
        nullptr, pat, nullptr, NPIX, sAT);

    // ---- join: bmm needs both V and att
    cudaStreamWaitEvent(0, evJ, 0);

    // outpre[c][n] = sum_m V[c][m] att[n][m]  (M=1024, N=4096, K=4096)
    // fp16 2-term, 2 CTAs/SM; SWAP raster; fused partial pooling; fp16 store.
    mma_gemm<4096, 4, true, 1, 2, 2><<<dim3(8, 32, BATCH), thr, SM_M1>>>(
        (const uint16_t*)pVh, (const uint16_t*)pVl, NPIX, sV,
        (const uint16_t*)pat, nullptr, NPIX, sAT,
        nullptr, pop, ppp, NPIX, sV);

    // tail
    gate_kernel<<<BATCH, thr>>>((const float*)ppp, Wca1, Wca2, (float*)pgate);
    scale_kernel<<<(int)(((size_t)BATCH * CCH * NPIX / 8) / 256), thr>>>(
        (const __half*)pop, (const float*)pgate, out);
}